// round 5
// baseline (speedup 1.0000x reference)
#include <cuda_runtime.h>
#include <cstdint>

// Problem constants (from reference): V=100000 vocab, D=128 dim
#define VOCAB 100000
#define DIM4  32   // 128 floats = 32 float4
#define TPW   8    // tokens per warp (MLP batching)

// Scratch: vocab -> candidate residual row. Validated in gather via
// ridx[row] == v, so no -1 fill pass is needed.
__device__ int g_remap[VOCAB];

__global__ void scatter_remap_kernel(const int* __restrict__ ridx, int R) {
    int i = blockIdx.x * blockDim.x + threadIdx.x;
    if (i < R) {
        g_remap[ridx[i]] = i;
    }
}

// Each warp handles TPW tokens. All index chains for the TPW tokens are
// independent -> front-batched loads (MLP=TPW) hide the 3-hop L2 latency
// chain. Each lane then copies one float4 per token (512B/warp/token).
__global__ __launch_bounds__(256)
void gather_kernel(const int* __restrict__ x,
                   const int* __restrict__ ridx,     // [R] sorted, L2-hot
                   const float4* __restrict__ pre,   // [V, 32] float4
                   const float4* __restrict__ res,   // [R, 32] float4
                   float4* __restrict__ out,         // [n_tok, 32] float4
                   int n_tok, int R) {
    int warp = (blockIdx.x * blockDim.x + threadIdx.x) >> 5;
    int lane = threadIdx.x & 31;
    long long base = (long long)warp * TPW;
    if (base >= n_tok) return;

    const float4* src[TPW];
    #pragma unroll
    for (int t = 0; t < TPW; t++) {
        long long tok = base + t;
        int v = (tok < n_tok) ? __ldg(x + tok) : 0;
        int r = g_remap[v];                                        // candidate row
        bool use_res = (r >= 0) && (r < R) && (__ldg(ridx + r) == v);
        src[t] = use_res ? (res + (long long)r * DIM4)
                         : (pre + (long long)v * DIM4);
    }

    float4 val[TPW];
    #pragma unroll
    for (int t = 0; t < TPW; t++)
        val[t] = __ldg(src[t] + lane);                             // 8 independent LDG.128

    #pragma unroll
    for (int t = 0; t < TPW; t++) {
        long long tok = base + t;
        if (tok < n_tok)
            __stcs(out + tok * DIM4 + lane, val[t]);               // streaming store
    }
}

extern "C" void kernel_launch(void* const* d_in, const int* in_sizes, int n_in,
                              void* d_out, int out_size) {
    // Input order per reference setup_inputs():
    //   0: x                    [B*S]   int32
    //   1: residual_index       [R]     int32
    //   2: pretrained_embedding [V*D]   float32
    //   3: residual_embedding   [R*D]   float32
    const int*    x    = (const int*)d_in[0];
    const int*    ridx = (const int*)d_in[1];
    const float4* pre  = (const float4*)d_in[2];
    const float4* res  = (const float4*)d_in[3];
    float4*       out  = (float4*)d_out;

    const int n_tok = in_sizes[0];          // B*S = 262144
    const int R     = in_sizes[1];          // 20000

    scatter_remap_kernel<<<(R + 127) / 128, 128>>>(ridx, R);

    const long long n_warps = ((long long)n_tok + TPW - 1) / TPW;
    const long long total_threads = n_warps * 32;
    const int block = 256;
    const int grid  = (int)((total_threads + block - 1) / block);
    gather_kernel<<<grid, block>>>(x, ridx, pre, res, out, n_tok, R);
}